// round 1
// baseline (speedup 1.0000x reference)
#include <cuda_runtime.h>
#include <math.h>

#define Bv   8
#define Nv   8192
#define Cv   64
#define Pv   2048
#define Kv   16
#define CF   67      // C + 3
#define CP   68      // padded row
#define H1v  64
#define H2v  128
#define EPSv 1e-5f

// scratch (static device globals: allocation-free)
__device__ float g_fx[(size_t)Bv * Nv * CP];   // packed [feat_t | xyz | 0] per point
__device__ int   g_knn[(size_t)Bv * Pv * Kv];  // knn indices

// ---------------------------------------------------------------------------
// Kernel A: transpose feat (B,C,N) -> fx[b][n][0..63], append xyz[3], pad 0
// ---------------------------------------------------------------------------
__global__ void pack_kernel(const float* __restrict__ xyz,
                            const float* __restrict__ feat) {
    __shared__ float t[64][33];
    int b  = blockIdx.y;
    int n0 = blockIdx.x * 32;
    int tx = threadIdx.x, ty = threadIdx.y;
    #pragma unroll
    for (int c0 = ty; c0 < 64; c0 += 16)
        t[c0][tx] = feat[((size_t)b * Cv + c0) * Nv + n0 + tx];
    __syncthreads();
    #pragma unroll
    for (int i = ty; i < 32; i += 16) {
        int n = n0 + i;
        float* row = &g_fx[((size_t)b * Nv + n) * CP];
        row[tx]      = t[tx][i];
        row[32 + tx] = t[32 + tx][i];
        if (tx < 3)  row[64 + tx] = xyz[((size_t)b * Nv + n) * 3 + tx];
        if (tx == 3) row[67] = 0.0f;
    }
}

// ---------------------------------------------------------------------------
// Kernel B: brute-force KNN (K=16 smallest d2), one thread per query,
// xyz tiled through shared memory (broadcast reads).
// ---------------------------------------------------------------------------
#define KNN_TILE 2048
__global__ void knn_kernel(const float* __restrict__ xyz) {
    __shared__ float sx[KNN_TILE], sy[KNN_TILE], sz[KNN_TILE];
    int b = blockIdx.y;
    int p = blockIdx.x * 64 + threadIdx.x;
    const float* xb = xyz + (size_t)b * Nv * 3;
    float qx = xb[p * 3 + 0], qy = xb[p * 3 + 1], qz = xb[p * 3 + 2];

    float bd[16]; int bi[16];
    #pragma unroll
    for (int i = 0; i < 16; i++) { bd[i] = 3.4e38f; bi[i] = 0; }
    float worst = 3.4e38f; int wslot = 0;

    for (int t0 = 0; t0 < Nv; t0 += KNN_TILE) {
        __syncthreads();
        for (int i = threadIdx.x; i < KNN_TILE; i += 64) {
            int base = (t0 + i) * 3;
            sx[i] = xb[base + 0];
            sy[i] = xb[base + 1];
            sz[i] = xb[base + 2];
        }
        __syncthreads();
        #pragma unroll 4
        for (int j = 0; j < KNN_TILE; j++) {
            float dx = qx - sx[j], dy = qy - sy[j], dz = qz - sz[j];
            float d2 = fmaf(dx, dx, fmaf(dy, dy, dz * dz));
            if (d2 < worst) {
                bd[wslot] = d2; bi[wslot] = t0 + j;
                worst = bd[0]; wslot = 0;
                #pragma unroll
                for (int i = 1; i < 16; i++)
                    if (bd[i] > worst) { worst = bd[i]; wslot = i; }
            }
        }
    }
    int* o = g_knn + ((size_t)b * Pv + p) * Kv;
    #pragma unroll
    for (int i = 0; i < 16; i++) o[i] = bi[i];
}

// ---------------------------------------------------------------------------
// Kernel C: fused gather + MLP(2 layers, folded BN) + max over K.
// One warp per point, 8 warps per block. All-K register tiling so weights are
// fetched from smem once per c-chunk. Layer1 center term folded out of k-loop.
// Dynamic smem layout (floats):
//   W1A: 0      (64*68)      W1D: 4352 (64*68)     W2S: 8704 (128*68)
//   S1:  17408  T1: 17472    S2: 17536  T2: 17664
//   NB:  17792  (8*16*68, reused as h-buffer)
//   CB:  26496  (8*68)       OB: 27040 (128*8)     total 28064 floats
// ---------------------------------------------------------------------------
__global__ void __launch_bounds__(256, 2) mlp_kernel(
    const float* __restrict__ W1, const float* __restrict__ b1,
    const float* __restrict__ g1, const float* __restrict__ be1,
    const float* __restrict__ m1, const float* __restrict__ v1,
    const float* __restrict__ W2, const float* __restrict__ b2,
    const float* __restrict__ g2, const float* __restrict__ be2,
    const float* __restrict__ m2, const float* __restrict__ v2,
    float* __restrict__ out) {
    extern __shared__ float sm[];
    float* W1A = sm;
    float* W1D = sm + 4352;
    float* W2S = sm + 8704;
    float* S1  = sm + 17408;
    float* T1  = sm + 17472;
    float* S2  = sm + 17536;
    float* T2  = sm + 17664;
    float* NB  = sm + 17792;
    float* CB  = sm + 26496;
    float* OB  = sm + 27040;

    int tid = threadIdx.x;

    // --- cooperative weight / fold loads ---
    for (int i = tid; i < 64 * CF; i += 256) {
        int o = i / CF, c = i % CF;
        float a = W1[o * 134 + c];
        W1A[o * CP + c] = a;
        W1D[o * CP + c] = W1[o * 134 + CF + c] - a;
    }
    for (int o = tid; o < 64; o += 256) { W1A[o * CP + 67] = 0.f; W1D[o * CP + 67] = 0.f; }
    for (int i = tid; i < 128 * 64; i += 256) {
        int j = i >> 6, o = i & 63;
        W2S[j * CP + o] = W2[i];
    }
    for (int j = tid; j < 128; j += 256) {
        W2S[j * CP + 64] = 0.f; W2S[j * CP + 65] = 0.f;
        W2S[j * CP + 66] = 0.f; W2S[j * CP + 67] = 0.f;
    }
    if (tid < 64) {
        float s = g1[tid] * rsqrtf(v1[tid] + EPSv);
        S1[tid] = s;
        T1[tid] = fmaf(s, b1[tid] - m1[tid], be1[tid]);
    }
    if (tid < 128) {
        float s = g2[tid] * rsqrtf(v2[tid] + EPSv);
        S2[tid] = s;
        T2[tid] = fmaf(s, b2[tid] - m2[tid], be2[tid]);
    }
    __syncthreads();

    int w = tid >> 5, lane = tid & 31;
    int pg = blockIdx.x * 8 + w;
    int b  = pg / Pv, p = pg % Pv;
    const float* fxb = g_fx + (size_t)b * Nv * CP;
    float* NBw = NB + w * (Kv * CP);
    float* CBw = CB + w * CP;

    // --- gather center + neighbors (contiguous float4 rows) ---
    if (lane < 17)
        ((float4*)CBw)[lane] = ((const float4*)(fxb + (size_t)p * CP))[lane];
    const int* kn = g_knn + ((size_t)b * Pv + p) * Kv;
    int myidx = (lane < Kv) ? kn[lane] : 0;
    #pragma unroll
    for (int it = 0; it < 9; it++) {
        int t = lane + it * 32;           // t in [0, 288), valid < 272
        int k = t / 17;
        int kk = (k < 15) ? k : 15;
        int nidx = __shfl_sync(0xffffffffu, myidx, kk);
        if (t < Kv * 17)
            ((float4*)NBw)[t] = ((const float4*)(fxb + (size_t)nidx * CP))[t - kk * 17];
    }
    __syncwarp();

    // --- layer1 base term: center · (W1b - W1a) (k-invariant) ---
    const float* wd0 = W1D + lane * CP;
    const float* wd1 = W1D + (lane + 32) * CP;
    float base0 = 0.f, base1 = 0.f;
    #pragma unroll
    for (int ci = 0; ci < 17; ci++) {
        float4 cv = ((const float4*)CBw)[ci];
        float4 a0 = ((const float4*)wd0)[ci];
        float4 a1 = ((const float4*)wd1)[ci];
        base0 = fmaf(cv.x, a0.x, fmaf(cv.y, a0.y, fmaf(cv.z, a0.z, fmaf(cv.w, a0.w, base0))));
        base1 = fmaf(cv.x, a1.x, fmaf(cv.y, a1.y, fmaf(cv.z, a1.z, fmaf(cv.w, a1.w, base1))));
    }

    // --- layer1 main: all 16 k in registers, 2 outputs per lane ---
    float acc0[16], acc1[16];
    #pragma unroll
    for (int k = 0; k < 16; k++) { acc0[k] = base0; acc1[k] = base1; }
    const float* wa0 = W1A + lane * CP;
    const float* wa1 = W1A + (lane + 32) * CP;
    #pragma unroll
    for (int ci = 0; ci < 17; ci++) {
        float4 w0 = ((const float4*)wa0)[ci];
        float4 w1 = ((const float4*)wa1)[ci];
        #pragma unroll
        for (int k = 0; k < 16; k++) {
            float4 v = ((const float4*)(NBw + k * CP))[ci];
            acc0[k] = fmaf(v.x, w0.x, fmaf(v.y, w0.y, fmaf(v.z, w0.z, fmaf(v.w, w0.w, acc0[k]))));
            acc1[k] = fmaf(v.x, w1.x, fmaf(v.y, w1.y, fmaf(v.z, w1.z, fmaf(v.w, w1.w, acc1[k]))));
        }
    }

    // --- act1, write h back into NB (cols 0..63) ---
    float s1a = S1[lane],      t1a = T1[lane];
    float s1b = S1[lane + 32], t1b = T1[lane + 32];
    __syncwarp();   // everyone done reading NB before overwrite
    #pragma unroll
    for (int k = 0; k < 16; k++) {
        NBw[k * CP + lane]      = fmaxf(fmaf(s1a, acc0[k], t1a), 0.f);
        NBw[k * CP + lane + 32] = fmaxf(fmaf(s1b, acc1[k], t1b), 0.f);
    }
    __syncwarp();

    // --- layer2: 4 outputs per lane, all 16 k in registers ---
    float acc2[16][4];
    #pragma unroll
    for (int k = 0; k < 16; k++) {
        acc2[k][0] = 0.f; acc2[k][1] = 0.f; acc2[k][2] = 0.f; acc2[k][3] = 0.f;
    }
    const float* wr0 = W2S + (lane)      * CP;
    const float* wr1 = W2S + (lane + 32) * CP;
    const float* wr2 = W2S + (lane + 64) * CP;
    const float* wr3 = W2S + (lane + 96) * CP;
    #pragma unroll
    for (int oi = 0; oi < 16; oi++) {
        float4 u0 = ((const float4*)wr0)[oi];
        float4 u1 = ((const float4*)wr1)[oi];
        float4 u2 = ((const float4*)wr2)[oi];
        float4 u3 = ((const float4*)wr3)[oi];
        #pragma unroll
        for (int k = 0; k < 16; k++) {
            float4 h = ((const float4*)(NBw + k * CP))[oi];
            acc2[k][0] = fmaf(h.x, u0.x, fmaf(h.y, u0.y, fmaf(h.z, u0.z, fmaf(h.w, u0.w, acc2[k][0]))));
            acc2[k][1] = fmaf(h.x, u1.x, fmaf(h.y, u1.y, fmaf(h.z, u1.z, fmaf(h.w, u1.w, acc2[k][1]))));
            acc2[k][2] = fmaf(h.x, u2.x, fmaf(h.y, u2.y, fmaf(h.z, u2.z, fmaf(h.w, u2.w, acc2[k][2]))));
            acc2[k][3] = fmaf(h.x, u3.x, fmaf(h.y, u3.y, fmaf(h.z, u3.z, fmaf(h.w, u3.w, acc2[k][3]))));
        }
    }

    // --- act2 + max over k (relu floor == init 0, relu commutes with max) ---
    float s20 = S2[lane],      t20 = T2[lane];
    float s21 = S2[lane + 32], t21 = T2[lane + 32];
    float s22 = S2[lane + 64], t22 = T2[lane + 64];
    float s23 = S2[lane + 96], t23 = T2[lane + 96];
    float mx0 = 0.f, mx1 = 0.f, mx2 = 0.f, mx3 = 0.f;
    #pragma unroll
    for (int k = 0; k < 16; k++) {
        mx0 = fmaxf(mx0, fmaf(s20, acc2[k][0], t20));
        mx1 = fmaxf(mx1, fmaf(s21, acc2[k][1], t21));
        mx2 = fmaxf(mx2, fmaf(s22, acc2[k][2], t22));
        mx3 = fmaxf(mx3, fmaf(s23, acc2[k][3], t23));
    }
    OB[(lane)      * 8 + w] = mx0;
    OB[(lane + 32) * 8 + w] = mx1;
    OB[(lane + 64) * 8 + w] = mx2;
    OB[(lane + 96) * 8 + w] = mx3;
    __syncthreads();

    // --- coalesced output: new_feat is (B, 128, P), offset after new_xyz ---
    int pbase = (blockIdx.x * 8) % Pv;
    int bblk  = (blockIdx.x * 8) / Pv;
    float* outF = out + (size_t)Bv * Pv * 3;
    for (int r = tid; r < 128 * 8; r += 256) {
        int j = r >> 3, pi = r & 7;
        outF[((size_t)bblk * H2v + j) * Pv + pbase + pi] = OB[r];
    }
}

// ---------------------------------------------------------------------------
// Kernel D: new_xyz copy + sample_idx
// ---------------------------------------------------------------------------
__global__ void tail_kernel(const float* __restrict__ xyz, float* __restrict__ out) {
    int i = blockIdx.x * 256 + threadIdx.x;
    const int NX = Bv * Pv * 3;
    if (i < NX) {
        int d = i % 3; int rem = i / 3; int p = rem % Pv; int b = rem / Pv;
        out[i] = xyz[((size_t)b * Nv + p) * 3 + d];
    } else if (i < NX + Bv * Pv) {
        int j = i - NX;
        out[(size_t)NX + (size_t)Bv * H2v * Pv + j] = (float)(j % Pv);
    }
}

// ---------------------------------------------------------------------------
extern "C" void kernel_launch(void* const* d_in, const int* in_sizes, int n_in,
                              void* d_out, int out_size) {
    const float* xyz  = (const float*)d_in[0];
    const float* feat = (const float*)d_in[1];
    const float* W1   = (const float*)d_in[2];
    const float* b1   = (const float*)d_in[3];
    const float* g1   = (const float*)d_in[4];
    const float* be1  = (const float*)d_in[5];
    const float* m1   = (const float*)d_in[6];
    const float* v1   = (const float*)d_in[7];
    const float* W2   = (const float*)d_in[8];
    const float* b2   = (const float*)d_in[9];
    const float* g2   = (const float*)d_in[10];
    const float* be2  = (const float*)d_in[11];
    const float* m2   = (const float*)d_in[12];
    const float* v2   = (const float*)d_in[13];
    float* out = (float*)d_out;

    const int SMEM_BYTES = 28064 * 4;
    cudaFuncSetAttribute(mlp_kernel, cudaFuncAttributeMaxDynamicSharedMemorySize,
                         SMEM_BYTES);

    pack_kernel<<<dim3(Nv / 32, Bv), dim3(32, 16)>>>(xyz, feat);
    knn_kernel<<<dim3(Pv / 64, Bv), 64>>>(xyz);
    mlp_kernel<<<Bv * Pv / 8, 256, SMEM_BYTES>>>(W1, b1, g1, be1, m1, v1,
                                                 W2, b2, g2, be2, m2, v2, out);
    tail_kernel<<<256, 256>>>(xyz, out);
}